// round 5
// baseline (speedup 1.0000x reference)
#include <cuda_runtime.h>

#define NUM_OUTPUTS 1032
#define D4 258              // 1032 floats = 258 float4 per weight row
#define CHUNK 86            // float4 per column chunk (3 chunks: 86*3 = 258)
#define NCHUNK 3
#define MAX_ACTIVE 32
#define BATCH 4096
#define THREADS 96          // 3 warps; lanes 0..85 active

__global__ __launch_bounds__(THREADS)
void ft_chunk_kernel(const int*    __restrict__ idx0,
                     const float*  __restrict__ val0,
                     const int*    __restrict__ idx1,
                     const float*  __restrict__ val1,
                     const float4* __restrict__ W4,
                     const float4* __restrict__ bias4,
                     float4*       __restrict__ out4)
{
    const int r     = blockIdx.x;          // 0..8191 : both feature sets fused
    const int chunk = blockIdx.y;          // 0..2    : slow scheduling dim -> phases
    const int tid   = threadIdx.x;

    const int*   idx;
    const float* val;
    int row;
    if (r < BATCH) { idx = idx0; val = val0; row = r; }
    else           { idx = idx1; val = val1; row = r - BATCH; }

    __shared__ size_t sOff[MAX_ACTIVE];    // pre-scaled row offsets (float4 units)
    __shared__ float  sVal[MAX_ACTIVE];
    if (tid < MAX_ACTIVE) {
        sOff[tid] = (size_t)idx[row * MAX_ACTIVE + tid] * D4;
        sVal[tid] = val[row * MAX_ACTIVE + tid];
    }
    __syncthreads();

    if (tid >= CHUNK) return;              // no barriers below

    const int c = chunk * CHUNK + tid;     // float4 column index, 0..257

    float4 a = bias4[c];

    #pragma unroll 8
    for (int k = 0; k < MAX_ACTIVE; ++k) {
        const float4 w = __ldg(W4 + sOff[k] + c);
        const float  v = sVal[k];
        a.x = fmaf(w.x, v, a.x);
        a.y = fmaf(w.y, v, a.y);
        a.z = fmaf(w.z, v, a.z);
        a.w = fmaf(w.w, v, a.w);
    }

    // Streaming store: written once, never re-read -> keep out of L2 so the
    // weight slice stays resident.
    __stcs(out4 + (size_t)r * D4 + c, a);
}

extern "C" void kernel_launch(void* const* d_in, const int* in_sizes, int n_in,
                              void* d_out, int out_size)
{
    // metadata order:
    //   0: feature_indices_0  int32  [4096, 32]
    //   1: feature_values_0   f32    [4096, 32]
    //   2: feature_indices_1  int32  [4096, 32]
    //   3: feature_values_1   f32    [4096, 32]
    //   4: merged_weight      f32    [45056, 1032]
    //   5: bias               f32    [1032]
    const int*    idx0 = (const int*)   d_in[0];
    const float*  val0 = (const float*) d_in[1];
    const int*    idx1 = (const int*)   d_in[2];
    const float*  val1 = (const float*) d_in[3];
    const float4* W4   = (const float4*)d_in[4];
    const float4* b4   = (const float4*)d_in[5];

    float4* out = (float4*)d_out;   // [8192, 1032] : out0 then out1

    dim3 grid(2 * BATCH, NCHUNK);
    ft_chunk_kernel<<<grid, THREADS>>>(idx0, val0, idx1, val1, W4, b4, out);
}